// round 5
// baseline (speedup 1.0000x reference)
#include <cuda_runtime.h>
#include <cstdint>

// Cost volume: out[b,d,h,w] = (1/C) * sum_c left[b,c,h,w] * right[b,c,h,w-d], 0 for w<d
// B=8, C=64, H=160, W=320, D=48.

#define BB 8
#define CC 64
#define HH 160
#define WW 320
#define DD 48

#define CK     8              // C-chunk per stage
#define NSTAGE (CC / CK)      // 8
#define PAD    48             // left zero-pad of right row
#define NT     160            // 4 d-groups (x12d) * 40 w-groups (x8w)

// Bank-conflict-free arithmetic swizzle: +4-float gap every 32 floats.
#define SW(i) ((i) + 4 * ((i) >> 5))
#define SLS  356              // left  row physical floats (SW(319)+1)
#define SRS  412              // right row physical floats (SW(367)+1)
// smem: 2*8*(356+412)*4 = 49152 B = 48 KB exactly -> 3 CTAs/SM = 144 KB.

typedef unsigned long long ull;

__device__ __forceinline__ ull pk(float lo, float hi) {
    ull v; asm("mov.b64 %0, {%1, %2};" : "=l"(v) : "f"(lo), "f"(hi)); return v;
}
__device__ __forceinline__ void upk(ull v, float& lo, float& hi) {
    asm("mov.b64 {%0, %1}, %2;" : "=f"(lo), "=f"(hi) : "l"(v));
}
__device__ __forceinline__ void ffma2(ull& d, ull a, ull b) {
    asm("fma.rn.f32x2 %0, %1, %2, %0;" : "+l"(d) : "l"(a), "l"(b));
}
__device__ __forceinline__ void cpasync16(void* dst_smem, const void* src) {
    uint32_t d = (uint32_t)__cvta_generic_to_shared(dst_smem);
    asm volatile("cp.async.cg.shared.global [%0], [%1], 16;" :: "r"(d), "l"(src) : "memory");
}

__global__ __launch_bounds__(NT, 3) void corvol_kernel(
    const float* __restrict__ left,
    const float* __restrict__ right,
    float* __restrict__ out)
{
    __shared__ __align__(16) float sL[2][CK][SLS];
    __shared__ __align__(16) float sR[2][CK][SRS];

    const int bh  = blockIdx.x;
    const int b   = bh / HH;
    const int h   = bh % HH;
    const int tid = threadIdx.x;

    const int dg = tid / 40;       // 0..3
    const int wg = tid % 40;       // 0..39
    const int d0 = dg * 12;
    const int w0 = wg * 8;

    const float* lb = left  + ((size_t)b * CC * HH + h) * WW;
    const float* rb = right + ((size_t)b * CC * HH + h) * WW;

    // Zero the right-pad region ONCE for both buffers.
    // 2 bufs * 8 rows * 12 float4 = 192 items.
    for (int i = tid; i < 2 * CK * (PAD / 4); i += NT) {
        const int buf = i / (CK * (PAD / 4));
        const int cc  = (i % (CK * (PAD / 4))) / (PAD / 4);
        const int v   = (i % (PAD / 4)) * 4;
        *(float4*)&sR[buf][cc][SW(v)] = make_float4(0.f, 0.f, 0.f, 0.f);
    }

    ull acc2[12][4];
    #pragma unroll
    for (int di = 0; di < 12; di++)
        #pragma unroll
        for (int j = 0; j < 4; j++)
            acc2[di][j] = 0ull;

    // r[k] = logical sR index q+k, q = PAD + w0 - d0 - 12 (multiple of 4, >= 0).
    // right[w-d] for w=w0+x, d=d0+di lives at r[x - di + 12], range [1,19].
    const int q   = PAD + w0 - d0 - 12;
    const int lw0 = SW(w0);
    int rq[5];
    #pragma unroll
    for (int t = 0; t < 5; t++) rq[t] = SW(q + 4 * t);

    // ---- stage 0 copy ----
    #pragma unroll
    for (int i = tid; i < CK * (WW / 4); i += NT) {
        const int cc = i / (WW / 4);
        const int v  = (i % (WW / 4)) * 4;
        const size_t goff = (size_t)cc * (HH * WW) + v;
        cpasync16(&sL[0][cc][SW(v)],       lb + goff);
        cpasync16(&sR[0][cc][SW(PAD + v)], rb + goff);
    }
    asm volatile("cp.async.commit_group;" ::: "memory");

    for (int s = 0; s < NSTAGE; s++) {
        const int cur = s & 1;
        if (s + 1 < NSTAGE) {
            const int nxt = (s + 1) & 1;
            const int c0n = (s + 1) * CK;
            #pragma unroll
            for (int i = tid; i < CK * (WW / 4); i += NT) {
                const int cc = i / (WW / 4);
                const int v  = (i % (WW / 4)) * 4;
                const size_t goff = (size_t)(c0n + cc) * (HH * WW) + v;
                cpasync16(&sL[nxt][cc][SW(v)],       lb + goff);
                cpasync16(&sR[nxt][cc][SW(PAD + v)], rb + goff);
            }
            asm volatile("cp.async.commit_group;" ::: "memory");
            asm volatile("cp.async.wait_group 1;"  ::: "memory");
        } else {
            asm volatile("cp.async.wait_group 0;"  ::: "memory");
        }
        __syncthreads();

        #pragma unroll
        for (int cc = 0; cc < CK; cc++) {
            float l[8];
            *(float4*)&l[0] = *(const float4*)&sL[cur][cc][lw0];
            *(float4*)&l[4] = *(const float4*)&sL[cur][cc][lw0 + 4];

            float r[20];
            #pragma unroll
            for (int t = 0; t < 5; t++)
                *(float4*)&r[4 * t] = *(const float4*)&sR[cur][cc][rq[t]];

            ull l2[4];
            #pragma unroll
            for (int j = 0; j < 4; j++) l2[j] = pk(l[2 * j], l[2 * j + 1]);
            ull e[10];   // e[k] = (r[2k], r[2k+1]), k = 1..9 used
            #pragma unroll
            for (int k = 1; k <= 9; k++) e[k] = pk(r[2 * k], r[2 * k + 1]);
            ull o[9];    // o[m] = (r[2m+1], r[2m+2]), m = 0..8 used
            #pragma unroll
            for (int m = 0; m <= 8; m++) o[m] = pk(r[2 * m + 1], r[2 * m + 2]);

            // acc2[di][j] covers (d0+di, w0+2j / w0+2j+1):
            //   pair starts at r[2j - di + 12]
            //   di even -> e[j + 6 - di/2]; di odd -> o[j + (11-di)/2]
            #pragma unroll
            for (int di = 0; di < 12; di++) {
                #pragma unroll
                for (int j = 0; j < 4; j++) {
                    const ull bop = (di & 1) ? o[j + (11 - di) / 2]
                                             : e[j + 6 - di / 2];
                    ffma2(acc2[di][j], l2[j], bop);
                }
            }
        }
        __syncthreads();
    }

    const float inv = 1.0f / (float)CC;
    #pragma unroll
    for (int di = 0; di < 12; di++) {
        float v[8];
        #pragma unroll
        for (int j = 0; j < 4; j++) {
            float lo, hi;
            upk(acc2[di][j], lo, hi);
            v[2 * j]     = lo * inv;
            v[2 * j + 1] = hi * inv;
        }
        float* op = out + (((size_t)b * DD + (d0 + di)) * HH + h) * WW + w0;
        *(float4*)op       = make_float4(v[0], v[1], v[2], v[3]);
        *(float4*)(op + 4) = make_float4(v[4], v[5], v[6], v[7]);
    }
}

extern "C" void kernel_launch(void* const* d_in, const int* in_sizes, int n_in,
                              void* d_out, int out_size)
{
    const float* left  = (const float*)d_in[0];
    const float* right = (const float*)d_in[1];
    float* out = (float*)d_out;
    corvol_kernel<<<BB * HH, NT>>>(left, right, out);
}